// round 1
// baseline (speedup 1.0000x reference)
#include <cuda_runtime.h>
#include <cstdint>

#define BATCHN 256
#define SEQLEN 512
#define NEMB   300
#define NHID   256

typedef unsigned long long ull;

// ---------- packed f32x2 helpers (sm_103a FFMA2 path) ----------
__device__ __forceinline__ void fma2(ull &d, ull a, ull b) {
    asm("fma.rn.f32x2 %0, %1, %2, %0;" : "+l"(d) : "l"(a), "l"(b));
}
__device__ __forceinline__ ull pack2(float x, float y) {
    ull r; asm("mov.b64 %0, {%1, %2};" : "=l"(r) : "f"(x), "f"(y)); return r;
}
__device__ __forceinline__ float2 unpack2(ull v) {
    float2 r; asm("mov.b64 {%0, %1}, %2;" : "=f"(r.x), "=f"(r.y) : "l"(v)); return r;
}
__device__ __forceinline__ float sigmoidf(float z) {
    return 1.0f / (1.0f + __expf(-z));
}

// Scratch: X[t][b][h] = (emb[words[b][t]] @ Wi), time-major. 128 MB device global.
__device__ float g_X[SEQLEN * BATCHN * NHID];

// =====================================================================
// Phase 1: X = gather(emb) @ Wi.   Rows r = t*256 + b (131072 rows), cols 256.
// 64x64 tiles, K=300 in chunks of 20, fp32x2 micro-kernel.
// =====================================================================
__global__ __launch_bounds__(256) void x_gemm_kernel(
    const int* __restrict__ words,
    const float* __restrict__ emb,
    const float* __restrict__ Wi)
{
    __shared__ int   wsm[64];
    __shared__ float As[20][64];   // [k][m]
    __shared__ float Bs[20][64];   // [k][n]

    const int tid   = threadIdx.x;
    const int rbase = blockIdx.x * 64;
    const int cbase = blockIdx.y * 64;

    if (tid < 64) {
        int r = rbase + tid;
        int t = r >> 8;          // row-major over (t, b) with B=256
        int b = r & 255;
        wsm[tid] = words[b * SEQLEN + t];
    }
    __syncthreads();

    const int tm = tid >> 4, tn = tid & 15;   // 16x16 thread grid, 4x4 micro-tile

    ull acc[4][2];
    #pragma unroll
    for (int i = 0; i < 4; i++) { acc[i][0] = 0ULL; acc[i][1] = 0ULL; }

    for (int k0 = 0; k0 < NEMB; k0 += 20) {
        // Gathered A tile: 64 rows x 20 k, float2 loads (emb rows 8B-aligned: 300 even)
        for (int i = tid; i < 640; i += 256) {
            int m = i / 10, kp = i % 10;
            float2 v = *(const float2*)&emb[(long long)wsm[m] * NEMB + k0 + 2 * kp];
            As[2 * kp][m]     = v.x;
            As[2 * kp + 1][m] = v.y;
        }
        for (int i = tid; i < 1280; i += 256) {
            int k = i >> 6, n = i & 63;
            Bs[k][n] = Wi[(k0 + k) * NHID + cbase + n];
        }
        __syncthreads();

        #pragma unroll
        for (int k = 0; k < 20; k++) {
            float4 av = *(const float4*)&As[k][tm * 4];
            float4 bv = *(const float4*)&Bs[k][tn * 4];
            ull b0 = pack2(bv.x, bv.y), b1 = pack2(bv.z, bv.w);
            ull a0 = pack2(av.x, av.x), a1 = pack2(av.y, av.y);
            ull a2 = pack2(av.z, av.z), a3 = pack2(av.w, av.w);
            fma2(acc[0][0], a0, b0); fma2(acc[0][1], a0, b1);
            fma2(acc[1][0], a1, b0); fma2(acc[1][1], a1, b1);
            fma2(acc[2][0], a2, b0); fma2(acc[2][1], a2, b1);
            fma2(acc[3][0], a3, b0); fma2(acc[3][1], a3, b1);
        }
        __syncthreads();
    }

    #pragma unroll
    for (int mi = 0; mi < 4; mi++) {
        int row = rbase + tm * 4 + mi;
        float2 lo = unpack2(acc[mi][0]);
        float2 hi = unpack2(acc[mi][1]);
        float4 o  = make_float4(lo.x, lo.y, hi.x, hi.y);
        *(float4*)&g_X[(long long)row * NHID + cbase + tn * 4] = o;
    }
}

// =====================================================================
// Phase 2: persistent recurrence. 128 CTAs x 128 threads, 2 batch rows/CTA.
// Wh rows 0..215 in smem (fp32, packed float4-over-k), rows 216..255 in regs.
// Thread j owns output cols j and j+128 for both rows. f32x2 along K.
// smem: 54*256 float4 (221184 B) + h[2][256] (2048 B) = 223232 B dynamic.
// =====================================================================
#define P2_SMEM (54 * 256 * 16 + 2 * 256 * 4)

__global__ void __launch_bounds__(128, 1) rnn_kernel(
    const float* __restrict__ Wh,
    const float* __restrict__ fcw,
    const float* __restrict__ fcb,
    float* __restrict__ out)
{
    extern __shared__ char smem[];
    ulonglong2* WhU  = (ulonglong2*)smem;                 // [54*256], pair-of-f32x2 over k
    float*      h_sm = (float*)(smem + 54 * 256 * 16);    // [2][256]

    const int j  = threadIdx.x;           // 0..127
    const int r0 = blockIdx.x * 2;
    const int r1 = r0 + 1;

    // Load Wh rows 0..215 into smem as float4-over-k: Wh4[k4][c] = Wh[4k4..4k4+3][c]
    for (int i = j; i < 54 * 256; i += 128) {
        int k4 = i >> 8, c = i & 255;
        int kr = 4 * k4;
        float4 v = make_float4(Wh[kr * NHID + c],       Wh[(kr + 1) * NHID + c],
                               Wh[(kr + 2) * NHID + c], Wh[(kr + 3) * NHID + c]);
        ((float4*)smem)[i] = v;
    }
    // Rows 216..255 live in registers: 10 k4-groups x 2 columns
    ulonglong2 whr[10][2];
    #pragma unroll
    for (int kk = 0; kk < 10; kk++) {
        int kr = 216 + 4 * kk;
        #pragma unroll
        for (int cc = 0; cc < 2; cc++) {
            int c = j + cc * 128;
            whr[kk][cc].x = pack2(Wh[kr * NHID + c],       Wh[(kr + 1) * NHID + c]);
            whr[kk][cc].y = pack2(Wh[(kr + 2) * NHID + c], Wh[(kr + 3) * NHID + c]);
        }
    }
    // h0 = 0
    h_sm[j] = 0.f; h_sm[j + 128] = 0.f; h_sm[j + 256] = 0.f; h_sm[j + 384] = 0.f;
    __syncthreads();

    // preload x for t=0
    float x00 = g_X[r0 * NHID + j];
    float x01 = g_X[r0 * NHID + j + 128];
    float x10 = g_X[r1 * NHID + j];
    float x11 = g_X[r1 * NHID + j + 128];

    const ulonglong2* H0 = (const ulonglong2*)(h_sm);
    const ulonglong2* H1 = (const ulonglong2*)(h_sm + 256);

    for (int t = 0; t < SEQLEN; t++) {
        ull a00 = 0, a01 = 0, a10 = 0, a11 = 0;

        #pragma unroll 6
        for (int k4 = 0; k4 < 54; k4++) {
            ulonglong2 w0 = WhU[k4 * 256 + j];
            ulonglong2 w1 = WhU[k4 * 256 + j + 128];
            ulonglong2 h0 = H0[k4];
            ulonglong2 h1 = H1[k4];
            fma2(a00, h0.x, w0.x); fma2(a00, h0.y, w0.y);
            fma2(a01, h0.x, w1.x); fma2(a01, h0.y, w1.y);
            fma2(a10, h1.x, w0.x); fma2(a10, h1.y, w0.y);
            fma2(a11, h1.x, w1.x); fma2(a11, h1.y, w1.y);
        }
        #pragma unroll
        for (int kk = 0; kk < 10; kk++) {
            ulonglong2 h0 = H0[54 + kk];
            ulonglong2 h1 = H1[54 + kk];
            fma2(a00, h0.x, whr[kk][0].x); fma2(a00, h0.y, whr[kk][0].y);
            fma2(a01, h0.x, whr[kk][1].x); fma2(a01, h0.y, whr[kk][1].y);
            fma2(a10, h1.x, whr[kk][0].x); fma2(a10, h1.y, whr[kk][0].y);
            fma2(a11, h1.x, whr[kk][1].x); fma2(a11, h1.y, whr[kk][1].y);
        }

        float2 s00 = unpack2(a00), s01 = unpack2(a01);
        float2 s10 = unpack2(a10), s11 = unpack2(a11);
        float hn00 = sigmoidf(x00 + s00.x + s00.y);
        float hn01 = sigmoidf(x01 + s01.x + s01.y);
        float hn10 = sigmoidf(x10 + s10.x + s10.y);
        float hn11 = sigmoidf(x11 + s11.x + s11.y);

        // prefetch next timestep's x (overlaps the barrier)
        if (t + 1 < SEQLEN) {
            const float* xp = g_X + (t + 1) * (BATCHN * NHID);
            x00 = xp[r0 * NHID + j];
            x01 = xp[r0 * NHID + j + 128];
            x10 = xp[r1 * NHID + j];
            x11 = xp[r1 * NHID + j + 128];
        }

        __syncthreads();                 // everyone done reading old h
        h_sm[j]       = hn00;
        h_sm[j + 128] = hn01;
        h_sm[j + 256] = hn10;
        h_sm[j + 384] = hn11;
        __syncthreads();                 // new h visible
    }

    // hidden -> out[256 + b*256 + h]
    out[256 + r0 * NHID + j]       = h_sm[j];
    out[256 + r0 * NHID + j + 128] = h_sm[j + 128];
    out[256 + r1 * NHID + j]       = h_sm[j + 256];
    out[256 + r1 * NHID + j + 128] = h_sm[j + 384];

    // sig = sigmoid(h @ fc_w + fc_b): warp 0 -> row r0, warp 1 -> row r1
    int w = j >> 5, l = j & 31;
    if (w < 2) {
        float s = 0.f;
        #pragma unroll
        for (int q = 0; q < 8; q++)
            s += h_sm[w * 256 + l + q * 32] * fcw[l + q * 32];
        #pragma unroll
        for (int o = 16; o; o >>= 1)
            s += __shfl_xor_sync(0xffffffffu, s, o);
        if (l == 0)
            out[r0 + w] = sigmoidf(s + fcb[0]);
    }
}

// =====================================================================
extern "C" void kernel_launch(void* const* d_in, const int* in_sizes, int n_in,
                              void* d_out, int out_size)
{
    const int*   words = (const int*)  d_in[0];
    const float* emb   = (const float*)d_in[1];
    const float* Wi    = (const float*)d_in[2];
    const float* Wh    = (const float*)d_in[3];
    const float* fcw   = (const float*)d_in[4];
    const float* fcb   = (const float*)d_in[5];
    float*       out   = (float*)d_out;

    cudaFuncSetAttribute(rnn_kernel, cudaFuncAttributeMaxDynamicSharedMemorySize, P2_SMEM);

    x_gemm_kernel<<<dim3((SEQLEN * BATCHN) / 64, NHID / 64), 256>>>(words, emb, Wi);
    rnn_kernel<<<BATCHN / 2, 128, P2_SMEM>>>(Wh, fcw, fcb, out);
}

// round 2
// speedup vs baseline: 1.3047x; 1.3047x over previous
#include <cuda_runtime.h>
#include <cstdint>

#define BATCHN 256
#define SEQLEN 512
#define NEMB   300
#define NHID   256

typedef unsigned long long ull;

// ---------- packed f32x2 helpers (sm_103a FFMA2 path) ----------
__device__ __forceinline__ void fma2(ull &d, ull a, ull b) {
    asm("fma.rn.f32x2 %0, %1, %2, %0;" : "+l"(d) : "l"(a), "l"(b));
}
__device__ __forceinline__ ull pack2(float x, float y) {
    ull r; asm("mov.b64 %0, {%1, %2};" : "=l"(r) : "f"(x), "f"(y)); return r;
}
__device__ __forceinline__ float2 unpack2(ull v) {
    float2 r; asm("mov.b64 {%0, %1}, %2;" : "=f"(r.x), "=f"(r.y) : "l"(v)); return r;
}
__device__ __forceinline__ float sigmoidf(float z) {
    return 1.0f / (1.0f + __expf(-z));
}

// Scratch: X[t][b][h] = (emb[words[b][t]] @ Wi), time-major. 128 MB device global.
__device__ float g_X[SEQLEN * BATCHN * NHID];

// =====================================================================
// Phase 1: X = gather(emb) @ Wi.  Rows r = t*256 + b (131072), cols 256.
// 128x64 tiles, K=300 in 15 chunks of 20, 8x4 micro-tile, reg-prefetch.
// =====================================================================
__global__ __launch_bounds__(256, 2) void x_gemm_kernel(
    const int* __restrict__ words,
    const float* __restrict__ emb,
    const float* __restrict__ Wi)
{
    __shared__ int wsm[128];
    __shared__ __align__(16) float As[20][128];   // [k][m]
    __shared__ __align__(16) float Bs[20][64];    // [k][n]

    const int tid   = threadIdx.x;
    const int rbase = blockIdx.x * 128;
    const int cbase = blockIdx.y * 64;

    if (tid < 128) {
        int r = rbase + tid;
        wsm[tid] = words[(r & 255) * SEQLEN + (r >> 8)];
    }
    __syncthreads();

    const int tm = tid >> 4, tn = tid & 15;   // 16x16 grid, 8x4 micro-tile

    ull acc[8][2];
    #pragma unroll
    for (int i = 0; i < 8; i++) { acc[i][0] = 0ULL; acc[i][1] = 0ULL; }

    // prefetch registers: A tile = 1280 float2 (5/thread), B tile = 1280 floats (5/thread)
    float2 pa[5];
    float  pb[5];

    // ---- load chunk 0 into regs ----
    #pragma unroll
    for (int l = 0; l < 5; l++) {
        int e = tid + l * 256;               // A element (float2): 1280 total
        int m = e / 10, kp = e % 10;
        pa[l] = *(const float2*)&emb[(long long)wsm[m] * NEMB + 2 * kp];
        int k = e >> 6, n = e & 63;          // B element
        pb[l] = Wi[k * NHID + cbase + n];
    }

    for (int c = 0; c < 15; c++) {
        // store prefetched chunk to smem
        #pragma unroll
        for (int l = 0; l < 5; l++) {
            int e = tid + l * 256;
            int m = e / 10, kp = e % 10;
            As[2 * kp][m]     = pa[l].x;
            As[2 * kp + 1][m] = pa[l].y;
            int k = e >> 6, n = e & 63;
            Bs[k][n] = pb[l];
        }
        __syncthreads();

        // prefetch next chunk (LDG latency hides under compute below)
        if (c + 1 < 15) {
            int k0 = (c + 1) * 20;
            #pragma unroll
            for (int l = 0; l < 5; l++) {
                int e = tid + l * 256;
                int m = e / 10, kp = e % 10;
                pa[l] = *(const float2*)&emb[(long long)wsm[m] * NEMB + k0 + 2 * kp];
                int k = e >> 6, n = e & 63;
                pb[l] = Wi[(k0 + k) * NHID + cbase + n];
            }
        }

        #pragma unroll
        for (int k = 0; k < 20; k++) {
            float4 a0 = *(const float4*)&As[k][tm * 8];
            float4 a1 = *(const float4*)&As[k][tm * 8 + 4];
            float4 bv = *(const float4*)&Bs[k][tn * 4];
            ull b0 = pack2(bv.x, bv.y), b1 = pack2(bv.z, bv.w);
            ull d0 = pack2(a0.x, a0.x), d1 = pack2(a0.y, a0.y);
            ull d2 = pack2(a0.z, a0.z), d3 = pack2(a0.w, a0.w);
            ull d4 = pack2(a1.x, a1.x), d5 = pack2(a1.y, a1.y);
            ull d6 = pack2(a1.z, a1.z), d7 = pack2(a1.w, a1.w);
            fma2(acc[0][0], d0, b0); fma2(acc[0][1], d0, b1);
            fma2(acc[1][0], d1, b0); fma2(acc[1][1], d1, b1);
            fma2(acc[2][0], d2, b0); fma2(acc[2][1], d2, b1);
            fma2(acc[3][0], d3, b0); fma2(acc[3][1], d3, b1);
            fma2(acc[4][0], d4, b0); fma2(acc[4][1], d4, b1);
            fma2(acc[5][0], d5, b0); fma2(acc[5][1], d5, b1);
            fma2(acc[6][0], d6, b0); fma2(acc[6][1], d6, b1);
            fma2(acc[7][0], d7, b0); fma2(acc[7][1], d7, b1);
        }
        __syncthreads();
    }

    #pragma unroll
    for (int mi = 0; mi < 8; mi++) {
        int row = rbase + tm * 8 + mi;
        float2 lo = unpack2(acc[mi][0]);
        float2 hi = unpack2(acc[mi][1]);
        float4 o  = make_float4(lo.x, lo.y, hi.x, hi.y);
        *(float4*)&g_X[(long long)row * NHID + cbase + tn * 4] = o;
    }
}

// =====================================================================
// Phase 2: recurrence. 128 CTAs x 256 threads, 2 batch rows/CTA,
// thread j owns column j for both rows.
// Wh rows 0..95 in smem (96 KB), rows 96..255 in registers (160 regs).
// h double-buffered in smem -> ONE barrier per step.
// =====================================================================
#define SQ 24   // smem k4-groups  (rows 0..95)
#define RQ 40   // reg  k4-groups  (rows 96..255)
#define P2_SMEM (SQ * 256 * 16 + 2 * 512 * 4)

__global__ void __launch_bounds__(256, 1) rnn_kernel(
    const float* __restrict__ Wh,
    const float* __restrict__ fcw,
    const float* __restrict__ fcb,
    float* __restrict__ out)
{
    extern __shared__ __align__(16) char smem[];
    ulonglong2* WhS = (ulonglong2*)smem;                    // [SQ*256]
    float*      hb  = (float*)(smem + SQ * 256 * 16);       // [2][2][256]

    const int j  = threadIdx.x;            // column 0..255
    const int r0 = blockIdx.x * 2;
    const int r1 = r0 + 1;

    // Wh rows 0..95 -> smem, packed float4-over-k: WhS[q][c] = Wh[4q..4q+3][c]
    for (int i = j; i < SQ * 256; i += 256) {
        int q = i >> 8, c = i & 255, kr = 4 * q;
        float4 v = make_float4(Wh[kr * NHID + c],       Wh[(kr + 1) * NHID + c],
                               Wh[(kr + 2) * NHID + c], Wh[(kr + 3) * NHID + c]);
        ((float4*)smem)[i] = v;
    }
    // Wh rows 96..255, col j -> registers
    ulonglong2 whr[RQ];
    #pragma unroll
    for (int q = 0; q < RQ; q++) {
        int kr = 96 + 4 * q;
        whr[q].x = pack2(Wh[kr * NHID + j],       Wh[(kr + 1) * NHID + j]);
        whr[q].y = pack2(Wh[(kr + 2) * NHID + j], Wh[(kr + 3) * NHID + j]);
    }
    hb[j] = 0.f; hb[256 + j] = 0.f;   // h0 = 0 in buffer 0
    __syncthreads();

    float x0 = g_X[r0 * NHID + j];
    float x1 = g_X[r1 * NHID + j];

    int buf = 0;
    for (int t = 0; t < SEQLEN; t++) {
        const ulonglong2* H0 = (const ulonglong2*)(hb + buf * 512);
        const ulonglong2* H1 = H0 + 64;

        ull a0 = 0, a1 = 0;
        #pragma unroll 8
        for (int q = 0; q < SQ; q++) {
            ulonglong2 w  = WhS[q * 256 + j];
            ulonglong2 h0 = H0[q];
            ulonglong2 h1 = H1[q];
            fma2(a0, h0.x, w.x); fma2(a0, h0.y, w.y);
            fma2(a1, h1.x, w.x); fma2(a1, h1.y, w.y);
        }
        #pragma unroll
        for (int q = 0; q < RQ; q++) {
            ulonglong2 h0 = H0[SQ + q];
            ulonglong2 h1 = H1[SQ + q];
            fma2(a0, h0.x, whr[q].x); fma2(a0, h0.y, whr[q].y);
            fma2(a1, h1.x, whr[q].x); fma2(a1, h1.y, whr[q].y);
        }

        float2 s0 = unpack2(a0), s1 = unpack2(a1);
        float hn0 = sigmoidf(x0 + s0.x + s0.y);
        float hn1 = sigmoidf(x1 + s1.x + s1.y);

        if (t + 1 < SEQLEN) {
            const float* xp = g_X + (t + 1) * (BATCHN * NHID);
            x0 = xp[r0 * NHID + j];
            x1 = xp[r1 * NHID + j];
        }

        int nb = buf ^ 1;
        hb[nb * 512 + j]       = hn0;
        hb[nb * 512 + 256 + j] = hn1;
        __syncthreads();
        buf = nb;
    }

    float hf0 = hb[buf * 512 + j];
    float hf1 = hb[buf * 512 + 256 + j];
    out[256 + r0 * NHID + j] = hf0;
    out[256 + r1 * NHID + j] = hf1;

    // sig = sigmoid(h @ fc_w + fc_b): warp 0 -> row r0, warp 1 -> row r1
    int w = j >> 5, l = j & 31;
    if (w < 2) {
        float s = 0.f;
        #pragma unroll
        for (int q = 0; q < 8; q++)
            s += hb[buf * 512 + w * 256 + l + q * 32] * fcw[l + q * 32];
        #pragma unroll
        for (int o = 16; o; o >>= 1)
            s += __shfl_xor_sync(0xffffffffu, s, o);
        if (l == 0)
            out[r0 + w] = sigmoidf(s + fcb[0]);
    }
}

// =====================================================================
extern "C" void kernel_launch(void* const* d_in, const int* in_sizes, int n_in,
                              void* d_out, int out_size)
{
    const int*   words = (const int*)  d_in[0];
    const float* emb   = (const float*)d_in[1];
    const float* Wi    = (const float*)d_in[2];
    const float* Wh    = (const float*)d_in[3];
    const float* fcw   = (const float*)d_in[4];
    const float* fcb   = (const float*)d_in[5];
    float*       out   = (float*)d_out;

    cudaFuncSetAttribute(rnn_kernel, cudaFuncAttributeMaxDynamicSharedMemorySize, P2_SMEM);

    x_gemm_kernel<<<dim3((SEQLEN * BATCHN) / 128, NHID / 64), 256>>>(words, emb, Wi);
    rnn_kernel<<<BATCHN / 2, 256, P2_SMEM>>>(Wh, fcw, fcb, out);
}